// round 9
// baseline (speedup 1.0000x reference)
#include <cuda_runtime.h>
#include <cuda.h>
#include <cuda_bf16.h>
#include <cstdint>

// ---------------- problem dims ----------------
#define B_DIM 32
#define T_DIM 4096
#define H_DIM 512
#define MTOT (B_DIM * T_DIM)   // 131072 token rows

// ---------------- K1 tiling: BM x BN tile, split-N partial scores ----------------
#define BM 128                 // rows per CTA
#define BN 128                 // N-chunk per CTA (4 chunks cover H=512)
#define NCHUNKS_N (H_DIM / BN) // 4
#define BK 32                  // K per pipeline stage
#define NKC (H_DIM / BK)       // 16 chunks
#define KPAD 36                // padded row stride in floats

// ---------------- stage-2 tiling ----------------
#define NCHUNK 64
#define TCH (T_DIM / NCHUNK)   // 64 t-rows per chunk CTA

// ---------------- K1 smem layout (bytes) ----------------
#define SM_V     0                              // 128 floats (this N-chunk of v)
#define SM_RED   512                            // 128 floats
#define SM_X     1024
#define X_STAGE  (BM * KPAD * 4)                // 18432
#define SM_W     (SM_X + 2 * X_STAGE)           // 37888
#define W_STAGE  (BN * KPAD * 4)                // 18432
#define SMEM_TOTAL (SM_W + 2 * W_STAGE)         // 74752  -> 2 CTAs/SM

// ---------------- scratch (no cudaMalloc allowed) ----------------
__device__ __align__(1024) float g_Wr[H_DIM * H_DIM];       // RNA-tf32-rounded W
__device__ float g_scores_p[NCHUNKS_N * MTOT];              // per-N-chunk partial scores
__device__ float g_scores[MTOT];                            // summed scores
__device__ float g_stats[B_DIM * 2];
__device__ float g_partial[B_DIM * NCHUNK * H_DIM];

// ============================================================================
// helpers
// ============================================================================
__device__ __forceinline__ uint32_t smem_u32(const void* p) {
    uint32_t a;
    asm("{ .reg .u64 t; cvta.to.shared.u64 t, %1; cvt.u32.u64 %0, t; }" : "=r"(a) : "l"(p));
    return a;
}

__device__ __forceinline__ void cp_async16(uint32_t dst, const void* src) {
    asm volatile("cp.async.cg.shared.global [%0], [%1], 16;" :: "r"(dst), "l"(src));
}
__device__ __forceinline__ void cp_commit() {
    asm volatile("cp.async.commit_group;");
}
template <int N>
__device__ __forceinline__ void cp_wait() {
    asm volatile("cp.async.wait_group %0;" :: "n"(N));
}

// round f32 -> tf32, result as raw b32 (for mma A/B operands)
__device__ __forceinline__ uint32_t to_tf32_bits(float x) {
    uint32_t y;
    asm("cvt.rna.tf32.f32 %0, %1;" : "=r"(y) : "f"(x));
    return y;
}

// tf32 mma: A/B operands are .b32 regs, D/C are .f32
__device__ __forceinline__ void mma_tf32(float* d, const uint32_t* a, const uint32_t* b) {
    asm volatile(
        "mma.sync.aligned.m16n8k8.row.col.f32.tf32.tf32.f32 "
        "{%0,%1,%2,%3}, {%4,%5,%6,%7}, {%8,%9}, {%0,%1,%2,%3};"
        : "+f"(d[0]), "+f"(d[1]), "+f"(d[2]), "+f"(d[3])
        : "r"(a[0]), "r"(a[1]), "r"(a[2]), "r"(a[3]), "r"(b[0]), "r"(b[1]));
}

// tanh(x) = 1 - 2/(exp(2x)+1)
__device__ __forceinline__ float fast_tanh(float x) {
    float e = __expf(2.0f * x);
    return 1.0f - __fdividef(2.0f, e + 1.0f);
}

// ============================================================================
// K0: round W to RNA-tf32  |  nop: launch-index padding so ncu lands on K1
// ============================================================================
__global__ void attn8701_round_w(const float* __restrict__ W) {
    int i = blockIdx.x * blockDim.x + threadIdx.x;
    uint32_t b = to_tf32_bits(W[i]);
    g_Wr[i] = __uint_as_float(b);
}

__global__ void attn8701_nop() {}

// ============================================================================
// K1: fused score GEMM, split-N (R6-proven mainloop):
//   scores_p[nc][m] = sum_{g in chunk nc} v[g] * tanh( sum_h x[m,h] W[g,h] )
// BM=128 x BN=128 tile, 2-stage cp.async pipeline, prefetch-before-wait
// ============================================================================
__global__ void __launch_bounds__(256, 2)
attn8701_scores(const float* __restrict__ x,
                const float* __restrict__ v) {
    extern __shared__ char smem[];
    uint32_t sb = smem_u32(smem);
    float* smf = (float*)smem;

    const int tid  = threadIdx.x;
    const int wid  = tid >> 5;
    const int lane = tid & 31;
    const int gq   = lane >> 2;      // groupID (0..7)
    const int tg   = lane & 3;       // thread-in-group (0..3)
    const int wr   = wid >> 2;       // warp row (0..1): m-offset 64*wr
    const int wc   = wid & 3;        // warp col (0..3): n-offset 32*wc
    const int nc     = blockIdx.x;               // N-chunk (0..3)
    const size_t m_base = (size_t)blockIdx.y * BM;
    const int n_base = nc * BN;

    // v chunk -> smem, zero reduction buffer
    if (tid < BN) smf[SM_V / 4 + tid] = v[n_base + tid];
    if (tid < BM) smf[SM_RED / 4 + tid] = 0.0f;

    // ---- prefetch: load k-chunk kc into stage s ----
    auto prefetch = [&](int kc, int s) {
        {   // x tile: 128 rows x 8 segs = 1024 tasks -> 4 per thread
            int i = tid;
            #pragma unroll
            for (int r = 0; r < 4; r++, i += 256) {
                int row = i >> 3, seg = i & 7;
                const float* src = x + (m_base + row) * H_DIM + kc * BK + seg * 4;
                cp_async16(sb + SM_X + s * X_STAGE + row * (KPAD * 4) + seg * 16, src);
            }
        }
        {   // W tile: 128 rows x 8 segs
            int i = tid;
            #pragma unroll
            for (int r = 0; r < 4; r++, i += 256) {
                int row = i >> 3, seg = i & 7;
                const float* src = g_Wr + (size_t)(n_base + row) * H_DIM + kc * BK + seg * 4;
                cp_async16(sb + SM_W + s * W_STAGE + row * (KPAD * 4) + seg * 16, src);
            }
        }
        cp_commit();
    };

    // accumulators: warp tile 64(m) x 32(n)
    float acc[4][4][4];
    #pragma unroll
    for (int mi = 0; mi < 4; mi++)
        #pragma unroll
        for (int ni = 0; ni < 4; ni++)
            #pragma unroll
            for (int c = 0; c < 4; c++) acc[mi][ni][c] = 0.0f;

    prefetch(0, 0);

    for (int kc = 0; kc < NKC; kc++) {
        if (kc + 1 < NKC) prefetch(kc + 1, (kc + 1) & 1);
        if (kc + 1 < NKC) cp_wait<1>(); else cp_wait<0>();
        __syncthreads();

        const float* xs = smf + (SM_X + (kc & 1) * X_STAGE) / 4;
        const float* ws = smf + (SM_W + (kc & 1) * W_STAGE) / 4;

        #pragma unroll
        for (int ks = 0; ks < BK / 8; ks++) {
            const int k0 = ks * 8;
            uint32_t a[4][4];
            #pragma unroll
            for (int mi = 0; mi < 4; mi++) {
                const float* xr0 = xs + (wr * 64 + mi * 16 + gq) * KPAD + k0 + tg;
                const float* xr1 = xr0 + 8 * KPAD;
                a[mi][0] = to_tf32_bits(xr0[0]);
                a[mi][1] = to_tf32_bits(xr1[0]);
                a[mi][2] = to_tf32_bits(xr0[4]);
                a[mi][3] = to_tf32_bits(xr1[4]);
            }
            #pragma unroll
            for (int ni = 0; ni < 4; ni++) {
                uint32_t b[2];
                const float* wrow = ws + (wc * 32 + ni * 8 + gq) * KPAD + k0 + tg;
                b[0] = __float_as_uint(wrow[0]);   // already tf32-rounded by K0
                b[1] = __float_as_uint(wrow[4]);
                #pragma unroll
                for (int mi = 0; mi < 4; mi++)
                    mma_tf32(acc[mi][ni], a[mi], b);
            }
        }
        __syncthreads();
    }

    // ---- epilogue: tanh, dot with v-chunk, reduce to per-row partial scores ----
    float svec[8];
    #pragma unroll
    for (int i = 0; i < 8; i++) svec[i] = 0.0f;

    const float* vs = smf + SM_V / 4;
    #pragma unroll
    for (int ni = 0; ni < 4; ni++) {
        int n0 = wc * 32 + ni * 8 + 2 * tg;
        float v0 = vs[n0], v1 = vs[n0 + 1];
        #pragma unroll
        for (int mi = 0; mi < 4; mi++) {
            svec[mi * 2 + 0] = fmaf(fast_tanh(acc[mi][ni][0]), v0,
                               fmaf(fast_tanh(acc[mi][ni][1]), v1, svec[mi * 2 + 0]));
            svec[mi * 2 + 1] = fmaf(fast_tanh(acc[mi][ni][2]), v0,
                               fmaf(fast_tanh(acc[mi][ni][3]), v1, svec[mi * 2 + 1]));
        }
    }
    #pragma unroll
    for (int i = 0; i < 8; i++) {
        svec[i] += __shfl_xor_sync(0xFFFFFFFF, svec[i], 1);
        svec[i] += __shfl_xor_sync(0xFFFFFFFF, svec[i], 2);
    }
    if (tg == 0) {
        #pragma unroll
        for (int mi = 0; mi < 4; mi++) {
            atomicAdd(&smf[SM_RED / 4 + wr * 64 + mi * 16 + gq],     svec[mi * 2 + 0]);
            atomicAdd(&smf[SM_RED / 4 + wr * 64 + mi * 16 + 8 + gq], svec[mi * 2 + 1]);
        }
    }
    __syncthreads();
    if (tid < BM)
        g_scores_p[(size_t)nc * MTOT + m_base + tid] = smf[SM_RED / 4 + tid];
}

// ============================================================================
// K2: sum partial scores, write summed scores, softmax stats per batch
// ============================================================================
__global__ void __launch_bounds__(1024)
attn8701_stats(float* __restrict__ scores) {
    __shared__ float red[1024];
    int b = blockIdx.x, tid = threadIdx.x;
    float sv[T_DIM / 1024];   // 4 score values per thread
    float m = -1e30f;
    #pragma unroll
    for (int r = 0; r < T_DIM / 1024; r++) {
        int i = r * 1024 + tid;
        size_t off = (size_t)b * T_DIM + i;
        float s = g_scores_p[off] + g_scores_p[MTOT + off]
                + g_scores_p[2 * (size_t)MTOT + off] + g_scores_p[3 * (size_t)MTOT + off];
        scores[off] = s;
        sv[r] = s;
        m = fmaxf(m, s);
    }
    red[tid] = m; __syncthreads();
    for (int st = 512; st > 0; st >>= 1) {
        if (tid < st) red[tid] = fmaxf(red[tid], red[tid + st]);
        __syncthreads();
    }
    m = red[0]; __syncthreads();
    float sum = 0.0f;
    #pragma unroll
    for (int r = 0; r < T_DIM / 1024; r++) sum += __expf(sv[r] - m);
    red[tid] = sum; __syncthreads();
    for (int st = 512; st > 0; st >>= 1) {
        if (tid < st) red[tid] += red[tid + st];
        __syncthreads();
    }
    if (tid == 0) { g_stats[b * 2] = m; g_stats[b * 2 + 1] = 1.0f / red[0]; }
}

// ============================================================================
// K3: partial weighted sums — partial[b,c,h] = sum_{t in chunk c} w_t x[b,t,h]
// ============================================================================
__global__ void __launch_bounds__(128)
attn8701_wsum(const float* __restrict__ x, const float* __restrict__ scores) {
    __shared__ float w[TCH];
    int b = blockIdx.x, c = blockIdx.y, tid = threadIdx.x;
    float m   = g_stats[b * 2];
    float inv = g_stats[b * 2 + 1];
    int t0 = c * TCH;
    if (tid < TCH)
        w[tid] = __expf(scores[(size_t)b * T_DIM + t0 + tid] - m) * inv;
    __syncthreads();
    const float4* xb = (const float4*)(x + ((size_t)b * T_DIM + t0) * H_DIM);
    float4 acc = make_float4(0.f, 0.f, 0.f, 0.f);
    #pragma unroll 8
    for (int t = 0; t < TCH; t++) {
        float4 xv = xb[(size_t)t * (H_DIM / 4) + tid];
        float wt = w[t];
        acc.x = fmaf(wt, xv.x, acc.x);
        acc.y = fmaf(wt, xv.y, acc.y);
        acc.z = fmaf(wt, xv.z, acc.z);
        acc.w = fmaf(wt, xv.w, acc.w);
    }
    ((float4*)(g_partial + ((size_t)b * NCHUNK + c) * H_DIM))[tid] = acc;
}

// ============================================================================
// K4: reduce partials -> out[b,h]
// ============================================================================
__global__ void attn8701_reduce(float* __restrict__ out) {
    int b = blockIdx.x, h = threadIdx.x;
    float s = 0.0f;
    #pragma unroll
    for (int c = 0; c < NCHUNK; c++)
        s += g_partial[((size_t)b * NCHUNK + c) * H_DIM + h];
    out[(size_t)b * H_DIM + h] = s;
}

// ============================================================================
// host side
// ============================================================================
extern "C" void kernel_launch(void* const* d_in, const int* in_sizes, int n_in,
                              void* d_out, int out_size) {
    const float* x = (const float*)d_in[0];   // (32, 4096, 512)
    const float* W = (const float*)d_in[1];   // (512, 512)
    const float* v = (const float*)d_in[2];   // (512,)
    float* out = (float*)d_out;               // (32, 512)
    (void)in_sizes; (void)n_in; (void)out_size;

    void* sc_ptr = nullptr;
    cudaGetSymbolAddress(&sc_ptr, g_scores);
    float* scores = (float*)sc_ptr;

    cudaFuncSetAttribute(attn8701_scores, cudaFuncAttributeMaxDynamicSharedMemorySize, SMEM_TOTAL);

    attn8701_round_w<<<(H_DIM * H_DIM) / 1024, 1024>>>(W);   // launch 0
    attn8701_nop<<<1, 32>>>();                               // launch 1 (pad)
    attn8701_nop<<<1, 32>>>();                               // launch 2 (pad)
    attn8701_scores<<<dim3(NCHUNKS_N, MTOT / BM), 256, SMEM_TOTAL>>>(x, v);  // launch 3 <- ncu target
    attn8701_stats<<<B_DIM, 1024>>>(scores);
    attn8701_wsum<<<dim3(B_DIM, NCHUNK), 128>>>(x, scores);
    attn8701_reduce<<<B_DIM, H_DIM>>>(out);
}

// round 10
// speedup vs baseline: 1.0542x; 1.0542x over previous
#include <cuda_runtime.h>
#include <cuda.h>
#include <cuda_bf16.h>
#include <cstdint>

// ---------------- problem dims ----------------
#define B_DIM 32
#define T_DIM 4096
#define H_DIM 512
#define MTOT (B_DIM * T_DIM)   // 131072 token rows

// ---------------- K1 tiling: BM x BN tile, split-N partial scores ----------------
#define BM 128                 // rows per CTA
#define BN 128                 // N-chunk per CTA (4 chunks cover H=512)
#define NCHUNKS_N (H_DIM / BN) // 4
#define BK 32                  // K per pipeline stage
#define NKC (H_DIM / BK)       // 16 chunks
#define KPAD 48                // padded row stride in floats (LDS.128 conflict-free: 48 mod 32 == 16)

// ---------------- stage-2 tiling ----------------
#define NCHUNK 64
#define TCH (T_DIM / NCHUNK)   // 64 t-rows per chunk CTA

// ---------------- K1 smem layout (bytes) ----------------
#define SM_V     0                              // 128 floats (this N-chunk of v)
#define SM_RED   512                            // 128 floats
#define SM_X     1024
#define X_STAGE  (BM * KPAD * 4)                // 24576
#define SM_W     (SM_X + 2 * X_STAGE)           // 50176
#define W_STAGE  (BN * KPAD * 4)                // 24576
#define SMEM_TOTAL (SM_W + 2 * W_STAGE)         // 99328 -> 2 CTAs/SM

// ---------------- scratch (no cudaMalloc allowed) ----------------
__device__ __align__(1024) float g_Wr[H_DIM * H_DIM];       // RNA-tf32-rounded W
__device__ float g_scores_p[NCHUNKS_N * MTOT];              // per-N-chunk partial scores
__device__ float g_scores[MTOT];                            // summed scores
__device__ float g_stats[B_DIM * 2];
__device__ float g_partial[B_DIM * NCHUNK * H_DIM];

// ============================================================================
// helpers
// ============================================================================
__device__ __forceinline__ uint32_t smem_u32(const void* p) {
    uint32_t a;
    asm("{ .reg .u64 t; cvta.to.shared.u64 t, %1; cvt.u32.u64 %0, t; }" : "=r"(a) : "l"(p));
    return a;
}

__device__ __forceinline__ void cp_async16(uint32_t dst, const void* src) {
    asm volatile("cp.async.cg.shared.global [%0], [%1], 16;" :: "r"(dst), "l"(src));
}
__device__ __forceinline__ void cp_commit() {
    asm volatile("cp.async.commit_group;");
}
template <int N>
__device__ __forceinline__ void cp_wait() {
    asm volatile("cp.async.wait_group %0;" :: "n"(N));
}

// round f32 -> tf32, result as raw b32
__device__ __forceinline__ uint32_t to_tf32_bits(float x) {
    uint32_t y;
    asm("cvt.rna.tf32.f32 %0, %1;" : "=r"(y) : "f"(x));
    return y;
}

// tf32 mma, operands passed as raw f32 bit patterns (HW reads tf32 = top 19 bits)
__device__ __forceinline__ void mma_tf32(float* d, float a0, float a1, float a2, float a3,
                                         float b0, float b1) {
    asm volatile(
        "mma.sync.aligned.m16n8k8.row.col.f32.tf32.tf32.f32 "
        "{%0,%1,%2,%3}, {%4,%5,%6,%7}, {%8,%9}, {%0,%1,%2,%3};"
        : "+f"(d[0]), "+f"(d[1]), "+f"(d[2]), "+f"(d[3])
        : "r"(__float_as_uint(a0)), "r"(__float_as_uint(a1)),
          "r"(__float_as_uint(a2)), "r"(__float_as_uint(a3)),
          "r"(__float_as_uint(b0)), "r"(__float_as_uint(b1)));
}

// tanh(x) = 1 - 2/(exp(2x)+1)
__device__ __forceinline__ float fast_tanh(float x) {
    float e = __expf(2.0f * x);
    return 1.0f - __fdividef(2.0f, e + 1.0f);
}

// ============================================================================
// K0: round W to RNA-tf32  |  nop: launch-index padding so ncu lands on K1
// ============================================================================
__global__ void attn8701_round_w(const float* __restrict__ W) {
    int i = blockIdx.x * blockDim.x + threadIdx.x;
    uint32_t b = to_tf32_bits(W[i]);
    g_Wr[i] = __uint_as_float(b);
}

__global__ void attn8701_nop() {}

// ============================================================================
// K1: fused score GEMM, split-N:
//   scores_p[nc][m] = sum_{g in chunk nc} v[g] * tanh( sum_h x[m,h] W[g,h] )
// k-permuted LDS.128 operand fetch: one float4 feeds TWO k8 mma steps.
// Logical k 4*tg..4*tg+3 fill phys slots {tg,tg+4} of mma pair — valid since
// the contraction is invariant under any k-permutation applied to A and B alike.
// ============================================================================
__global__ void __launch_bounds__(256, 2)
attn8701_scores(const float* __restrict__ x,
                const float* __restrict__ v) {
    extern __shared__ char smem[];
    uint32_t sb = smem_u32(smem);
    float* smf = (float*)smem;

    const int tid  = threadIdx.x;
    const int wid  = tid >> 5;
    const int lane = tid & 31;
    const int gq   = lane >> 2;      // groupID (0..7)
    const int tg   = lane & 3;       // thread-in-group (0..3)
    const int wr   = wid >> 2;       // warp row (0..1): m-offset 64*wr
    const int wc   = wid & 3;        // warp col (0..3): n-offset 32*wc
    const int nc     = blockIdx.x;               // N-chunk (0..3)
    const size_t m_base = (size_t)blockIdx.y * BM;
    const int n_base = nc * BN;

    // v chunk -> smem, zero reduction buffer
    if (tid < BN) smf[SM_V / 4 + tid] = v[n_base + tid];
    if (tid < BM) smf[SM_RED / 4 + tid] = 0.0f;

    // ---- prefetch: load k-chunk kc into stage s ----
    auto prefetch = [&](int kc, int s) {
        {   // x tile: 128 rows x 8 segs = 1024 tasks -> 4 per thread
            int i = tid;
            #pragma unroll
            for (int r = 0; r < 4; r++, i += 256) {
                int row = i >> 3, seg = i & 7;
                const float* src = x + (m_base + row) * H_DIM + kc * BK + seg * 4;
                cp_async16(sb + SM_X + s * X_STAGE + row * (KPAD * 4) + seg * 16, src);
            }
        }
        {   // W tile: 128 rows x 8 segs
            int i = tid;
            #pragma unroll
            for (int r = 0; r < 4; r++, i += 256) {
                int row = i >> 3, seg = i & 7;
                const float* src = g_Wr + (size_t)(n_base + row) * H_DIM + kc * BK + seg * 4;
                cp_async16(sb + SM_W + s * W_STAGE + row * (KPAD * 4) + seg * 16, src);
            }
        }
        cp_commit();
    };

    // accumulators: warp tile 64(m) x 32(n)
    float acc[4][4][4];
    #pragma unroll
    for (int mi = 0; mi < 4; mi++)
        #pragma unroll
        for (int ni = 0; ni < 4; ni++)
            #pragma unroll
            for (int c = 0; c < 4; c++) acc[mi][ni][c] = 0.0f;

    prefetch(0, 0);

    for (int kc = 0; kc < NKC; kc++) {
        if (kc + 1 < NKC) prefetch(kc + 1, (kc + 1) & 1);
        if (kc + 1 < NKC) cp_wait<1>(); else cp_wait<0>();
        __syncthreads();

        const float* xs = smf + (SM_X + (kc & 1) * X_STAGE) / 4;
        const float* ws = smf + (SM_W + (kc & 1) * W_STAGE) / 4;

        #pragma unroll
        for (int kh = 0; kh < 2; kh++) {   // two 16-k halves per chunk
            const int koff = kh * 16 + tg * 4;
            // B fragments: one float4 per ni covers both mma k-steps
            float4 bf[4];
            #pragma unroll
            for (int ni = 0; ni < 4; ni++)
                bf[ni] = *(const float4*)(ws + (wc * 32 + ni * 8 + gq) * KPAD + koff);
            #pragma unroll
            for (int mi = 0; mi < 4; mi++) {
                const float* xr = xs + (wr * 64 + mi * 16 + gq) * KPAD + koff;
                float4 a0 = *(const float4*)(xr);             // row gq
                float4 a1 = *(const float4*)(xr + 8 * KPAD);  // row gq+8
                #pragma unroll
                for (int ni = 0; ni < 4; ni++) {
                    mma_tf32(acc[mi][ni], a0.x, a1.x, a0.y, a1.y, bf[ni].x, bf[ni].y);
                    mma_tf32(acc[mi][ni], a0.z, a1.z, a0.w, a1.w, bf[ni].z, bf[ni].w);
                }
            }
        }
        __syncthreads();
    }

    // ---- epilogue: tanh, dot with v-chunk, reduce to per-row partial scores ----
    float svec[8];
    #pragma unroll
    for (int i = 0; i < 8; i++) svec[i] = 0.0f;

    const float* vs = smf + SM_V / 4;
    #pragma unroll
    for (int ni = 0; ni < 4; ni++) {
        int n0 = wc * 32 + ni * 8 + 2 * tg;
        float v0 = vs[n0], v1 = vs[n0 + 1];
        #pragma unroll
        for (int mi = 0; mi < 4; mi++) {
            svec[mi * 2 + 0] = fmaf(fast_tanh(acc[mi][ni][0]), v0,
                               fmaf(fast_tanh(acc[mi][ni][1]), v1, svec[mi * 2 + 0]));
            svec[mi * 2 + 1] = fmaf(fast_tanh(acc[mi][ni][2]), v0,
                               fmaf(fast_tanh(acc[mi][ni][3]), v1, svec[mi * 2 + 1]));
        }
    }
    #pragma unroll
    for (int i = 0; i < 8; i++) {
        svec[i] += __shfl_xor_sync(0xFFFFFFFF, svec[i], 1);
        svec[i] += __shfl_xor_sync(0xFFFFFFFF, svec[i], 2);
    }
    if (tg == 0) {
        #pragma unroll
        for (int mi = 0; mi < 4; mi++) {
            atomicAdd(&smf[SM_RED / 4 + wr * 64 + mi * 16 + gq],     svec[mi * 2 + 0]);
            atomicAdd(&smf[SM_RED / 4 + wr * 64 + mi * 16 + 8 + gq], svec[mi * 2 + 1]);
        }
    }
    __syncthreads();
    if (tid < BM)
        g_scores_p[(size_t)nc * MTOT + m_base + tid] = smf[SM_RED / 4 + tid];
}

// ============================================================================
// K2: sum partial scores, write summed scores, softmax stats per batch
// ============================================================================
__global__ void __launch_bounds__(1024)
attn8701_stats(float* __restrict__ scores) {
    __shared__ float red[1024];
    int b = blockIdx.x, tid = threadIdx.x;
    float sv[T_DIM / 1024];   // 4 score values per thread
    float m = -1e30f;
    #pragma unroll
    for (int r = 0; r < T_DIM / 1024; r++) {
        int i = r * 1024 + tid;
        size_t off = (size_t)b * T_DIM + i;
        float s = g_scores_p[off] + g_scores_p[MTOT + off]
                + g_scores_p[2 * (size_t)MTOT + off] + g_scores_p[3 * (size_t)MTOT + off];
        scores[off] = s;
        sv[r] = s;
        m = fmaxf(m, s);
    }
    red[tid] = m; __syncthreads();
    for (int st = 512; st > 0; st >>= 1) {
        if (tid < st) red[tid] = fmaxf(red[tid], red[tid + st]);
        __syncthreads();
    }
    m = red[0]; __syncthreads();
    float sum = 0.0f;
    #pragma unroll
    for (int r = 0; r < T_DIM / 1024; r++) sum += __expf(sv[r] - m);
    red[tid] = sum; __syncthreads();
    for (int st = 512; st > 0; st >>= 1) {
        if (tid < st) red[tid] += red[tid + st];
        __syncthreads();
    }
    if (tid == 0) { g_stats[b * 2] = m; g_stats[b * 2 + 1] = 1.0f / red[0]; }
}

// ============================================================================
// K3: partial weighted sums — partial[b,c,h] = sum_{t in chunk c} w_t x[b,t,h]
// ============================================================================
__global__ void __launch_bounds__(128)
attn8701_wsum(const float* __restrict__ x, const float* __restrict__ scores) {
    __shared__ float w[TCH];
    int b = blockIdx.x, c = blockIdx.y, tid = threadIdx.x;
    float m   = g_stats[b * 2];
    float inv = g_stats[b * 2 + 1];
    int t0 = c * TCH;
    if (tid < TCH)
        w[tid] = __expf(scores[(size_t)b * T_DIM + t0 + tid] - m) * inv;
    __syncthreads();
    const float4* xb = (const float4*)(x + ((size_t)b * T_DIM + t0) * H_DIM);
    float4 acc = make_float4(0.f, 0.f, 0.f, 0.f);
    #pragma unroll 8
    for (int t = 0; t < TCH; t++) {
        float4 xv = xb[(size_t)t * (H_DIM / 4) + tid];
        float wt = w[t];
        acc.x = fmaf(wt, xv.x, acc.x);
        acc.y = fmaf(wt, xv.y, acc.y);
        acc.z = fmaf(wt, xv.z, acc.z);
        acc.w = fmaf(wt, xv.w, acc.w);
    }
    ((float4*)(g_partial + ((size_t)b * NCHUNK + c) * H_DIM))[tid] = acc;
}

// ============================================================================
// K4: reduce partials -> out[b,h]
// ============================================================================
__global__ void attn8701_reduce(float* __restrict__ out) {
    int b = blockIdx.x, h = threadIdx.x;
    float s = 0.0f;
    #pragma unroll
    for (int c = 0; c < NCHUNK; c++)
        s += g_partial[((size_t)b * NCHUNK + c) * H_DIM + h];
    out[(size_t)b * H_DIM + h] = s;
}

// ============================================================================
// host side
// ============================================================================
extern "C" void kernel_launch(void* const* d_in, const int* in_sizes, int n_in,
                              void* d_out, int out_size) {
    const float* x = (const float*)d_in[0];   // (32, 4096, 512)
    const float* W = (const float*)d_in[1];   // (512, 512)
    const float* v = (const float*)d_in[2];   // (512,)
    float* out = (float*)d_out;               // (32, 512)
    (void)in_sizes; (void)n_in; (void)out_size;

    void* sc_ptr = nullptr;
    cudaGetSymbolAddress(&sc_ptr, g_scores);
    float* scores = (float*)sc_ptr;

    cudaFuncSetAttribute(attn8701_scores, cudaFuncAttributeMaxDynamicSharedMemorySize, SMEM_TOTAL);

    attn8701_round_w<<<(H_DIM * H_DIM) / 1024, 1024>>>(W);   // launch 0
    attn8701_nop<<<1, 32>>>();                               // launch 1 (pad)
    attn8701_nop<<<1, 32>>>();                               // launch 2 (pad)
    attn8701_scores<<<dim3(NCHUNKS_N, MTOT / BM), 256, SMEM_TOTAL>>>(x, v);  // launch 3 <- ncu target
    attn8701_stats<<<B_DIM, 1024>>>(scores);
    attn8701_wsum<<<dim3(B_DIM, NCHUNK), 128>>>(x, scores);
    attn8701_reduce<<<B_DIM, H_DIM>>>(out);
}